// round 16
// baseline (speedup 1.0000x reference)
#include <cuda_runtime.h>
#include <cuda_bf16.h>
#include <cstdint>

// DifferentiableTopKSelector == per-row hard top-32 mask of raw scores
// (straight-through estimator is value-identical to hard_mask; `u` is dead).
//
// Round 16: 2-row software pipeline per CTA. After row A's candidates are
// pushed to smem, the payload registers are dead -> issue row B's loads
// BEFORE ranking row A, so row B's 16 KB/thread-block streams during the
// rank/scatter phase. Ping-pong candidate buffers; 1.5 barriers/row
// (was 2); half the CTA turnovers. R12 machinery otherwise: GUESS=2.3,
// warp-aggregated push (1 atomic/warp), exact stable rank on 64-bit
// composite keys (jax.lax.top_k tie-break), serial exact fallback guard.

static constexpr int COLS = 8192;
static constexpr int NT   = 512;
static constexpr int VPT  = COLS / 4 / NT;   // 4 float4 per thread
static constexpr int CAP  = 256;
static constexpr int KSEL = 32;
#define GUESS 2.3f

__device__ __forceinline__ unsigned long long pack_key(float v, unsigned idx) {
    // v > GUESS > 0: float bits compare as unsigned. Inverted index makes
    // larger composite == (larger value, then smaller index).
    return ((unsigned long long)__float_as_uint(v) << 32)
         | (unsigned long long)(COLS - 1u - idx);
}

// Warp-aggregated candidate push: one shared atomic per warp.
__device__ __forceinline__ void push_cands(const float4* v, unsigned n, int t,
                                           unsigned long long* cbuf, int* cnt) {
    unsigned incl = n;
    #pragma unroll
    for (int d = 1; d < 32; d <<= 1) {
        unsigned o = __shfl_up_sync(0xFFFFFFFFu, incl, d);
        if ((t & 31) >= d) incl += o;
    }
    const unsigned total = __shfl_sync(0xFFFFFFFFu, incl, 31);
    if (!total) return;
    unsigned base = 0;
    if ((t & 31) == 31) base = (unsigned)atomicAdd(cnt, (int)total);
    base = __shfl_sync(0xFFFFFFFFu, base, 31);
    if (n && base + total <= CAP) {
        unsigned pos = base + incl - n;
        #pragma unroll
        for (int it = 0; it < VPT; ++it) {
            const unsigned bb = (unsigned)((t + it * NT) * 4);
            if (v[it].x > GUESS) cbuf[pos++] = pack_key(v[it].x, bb + 0u);
            if (v[it].y > GUESS) cbuf[pos++] = pack_key(v[it].y, bb + 1u);
            if (v[it].z > GUESS) cbuf[pos++] = pack_key(v[it].z, bb + 2u);
            if (v[it].w > GUESS) cbuf[pos++] = pack_key(v[it].w, bb + 3u);
        }
    }
}

__device__ __forceinline__ unsigned count_hits(const float4* v) {
    unsigned n = 0;
    #pragma unroll
    for (int it = 0; it < VPT; ++it)
        n += (v[it].x > GUESS) + (v[it].y > GUESS)
           + (v[it].z > GUESS) + (v[it].w > GUESS);
    return n;
}

// Exact stable rank among cnt candidates; scatter 1.0f at the 32 winners.
__device__ __forceinline__ void rank_scatter(const unsigned long long* cbuf,
                                             int cnt, int t,
                                             float* __restrict__ rowout) {
    if (t < cnt) {
        const unsigned long long ci = cbuf[t];
        int r = 0;
        for (int j = 0; j < cnt; ++j)
            r += (cbuf[j] > ci);                     // LDS.64 broadcast
        if (r < KSEL)
            rowout[COLS - 1u - (unsigned)(ci & 0xFFFFFFFFull)] = 1.0f;
    }
}

// Exact serial guard for arbitrary inputs (never taken for N(0,1) rows).
__device__ void serial_topk(const float* __restrict__ rowin,
                            float* __restrict__ rowout) {
    float    bk[KSEL];
    unsigned bi[KSEL];
    #pragma unroll
    for (int i = 0; i < KSEL; ++i) { bk[i] = -INFINITY; bi[i] = 0u; }
    for (int i = 0; i < COLS; ++i) {
        float vv = rowin[i];
        if (vv > bk[KSEL - 1]) {                     // strict > == stable
            int p = KSEL - 1;
            while (p > 0 && vv > bk[p - 1]) {
                bk[p] = bk[p - 1]; bi[p] = bi[p - 1]; --p;
            }
            bk[p] = vv; bi[p] = (unsigned)i;
        }
    }
    for (int i = 0; i < KSEL; ++i) rowout[bi[i]] = 1.0f;
}

__global__ void __launch_bounds__(NT)
topk_mask_kernel(const float* __restrict__ scores, float* __restrict__ out,
                 int rows) {
    __shared__ unsigned long long cand[2][CAP];      // 4 KB ping-pong
    __shared__ int s_cnt[2];

    const int t = threadIdx.x;
    if (t < 2) s_cnt[t] = 0;                         // ordered by barrier #1

    const int r0 = blockIdx.x * 2;
    const int r1 = r0 + 1;
    const bool has1 = (r1 < rows);
    const size_t off0 = (size_t)r0 * COLS;
    const size_t off1 = off0 + COLS;
    const float4 z = make_float4(0.f, 0.f, 0.f, 0.f);

    // ======== row A: load burst + zero fill ========
    float4 v[VPT];
    {
        const float4* in0 = (const float4*)(scores + off0);
        float4*       o0  = (float4*)(out + off0);
        #pragma unroll
        for (int it = 0; it < VPT; ++it)
            v[it] = __ldcs(in0 + t + it * NT);
        #pragma unroll
        for (int it = 0; it < VPT; ++it)
            __stcs(o0 + t + it * NT, z);
    }

    const unsigned nA = count_hits(v);
    __syncthreads();                                 // s_cnt init visible
    push_cands(v, nA, t, cand[0], &s_cnt[0]);
    __syncthreads();
    const int cntA = s_cnt[0];

    // ======== row B: load burst issues NOW (v[] is dead after push) ========
    if (has1) {
        const float4* in1 = (const float4*)(scores + off1);
        float4*       o1  = (float4*)(out + off1);
        #pragma unroll
        for (int it = 0; it < VPT; ++it)
            v[it] = __ldcs(in1 + t + it * NT);
        #pragma unroll
        for (int it = 0; it < VPT; ++it)
            __stcs(o1 + t + it * NT, z);
    }

    // ======== rank A while row B streams ========
    if (cntA >= KSEL && cntA <= CAP)
        rank_scatter(cand[0], cntA, t, out + off0);
    else if (t == 0)
        serial_topk(scores + off0, out + off0);

    // ======== row B: detect / push / rank ========
    if (has1) {
        const unsigned nB = count_hits(v);
        // cand[1]/s_cnt[1] disjoint from rank-A's reads -> no barrier needed
        push_cands(v, nB, t, cand[1], &s_cnt[1]);
        __syncthreads();
        const int cntB = s_cnt[1];
        if (cntB >= KSEL && cntB <= CAP)
            rank_scatter(cand[1], cntB, t, out + off1);
        else if (t == 0)
            serial_topk(scores + off1, out + off1);
    }
}

extern "C" void kernel_launch(void* const* d_in, const int* in_sizes, int n_in,
                              void* d_out, int out_size) {
    const float* scores = (const float*)d_in[0];   // (4096, 8192) fp32
    // d_in[1] (u) is mathematically dead: output == hard top-k mask of scores.
    float* out = (float*)d_out;
    const int rows = out_size / COLS;              // 4096
    const int grid = (rows + 1) / 2;               // 2 rows per CTA
    topk_mask_kernel<<<grid, NT>>>(scores, out, rows);
}